// round 2
// baseline (speedup 1.0000x reference)
#include <cuda_runtime.h>

#define NN 8192
#define DH 64
#define BI 32
#define BJ 64
#define TPB 256
#define NCHUNK (NN / BJ)

// ---------------- device scratch (no allocation allowed) ----------------
__device__ float g_Wh[NN * DH];
__device__ float g_x[NN * DH];
__device__ float g_src[NN], g_dst[NN];
__device__ float g_A[NN], g_B[NN], g_C[NN], g_D[NN];

// ---------------- packed f32x2 helpers (Blackwell FFMA2) ----------------
__device__ __forceinline__ unsigned long long pack2(float x, float y) {
    unsigned long long r;
    asm("mov.b64 %0, {%1, %2};" : "=l"(r) : "f"(x), "f"(y));
    return r;
}
__device__ __forceinline__ void unpack2(unsigned long long v, float& x, float& y) {
    asm("mov.b64 {%0, %1}, %2;" : "=f"(x), "=f"(y) : "l"(v));
}
__device__ __forceinline__ unsigned long long ffma2(unsigned long long a,
                                                    unsigned long long b,
                                                    unsigned long long c) {
    unsigned long long d;
    asm("fma.rn.f32x2 %0, %1, %2, %3;" : "=l"(d) : "l"(a), "l"(b), "l"(c));
    return d;
}

// ---------------- prep: Wh = x@W^T + b ; src/dst ; exp factors ----------------
// grid 64 x 128 threads, one node-row per thread.
__global__ void prep_kernel(const float* __restrict__ xa, const float* __restrict__ xb,
                            const float* __restrict__ Wm, const float* __restrict__ bv,
                            const float* __restrict__ av, int use_gx) {
    __shared__ float Ws[DH * DH];
    __shared__ float as_[2 * DH];
    __shared__ float bs[DH];
    int t = threadIdx.x;
    for (int k = t; k < DH * DH; k += 128) Ws[k] = Wm[k];
    if (t < 2 * DH) as_[t] = av[t];
    if (t < DH) bs[t] = bv[t];
    __syncthreads();

    int row = blockIdx.x * 128 + t;
    const float* xr;
    if (use_gx) xr = g_x + (size_t)row * DH;
    else xr = (row < NN / 2) ? xa + (size_t)row * DH
                             : xb + (size_t)(row - NN / 2) * DH;

    float x[DH];
#pragma unroll
    for (int q = 0; q < DH / 4; q++) {
        float4 v = ((const float4*)xr)[q];
        x[4 * q + 0] = v.x; x[4 * q + 1] = v.y; x[4 * q + 2] = v.z; x[4 * q + 3] = v.w;
    }

    float srcv = 0.f, dstv = 0.f;
    float4 buf;
    float* whrow = g_Wh + (size_t)row * DH;
    for (int i = 0; i < DH; i++) {
        float acc = bs[i];
#pragma unroll
        for (int j = 0; j < DH; j++) acc += x[j] * Ws[i * DH + j];
        srcv += acc * as_[i];
        dstv += acc * as_[DH + i];
        ((float*)&buf)[i & 3] = acc;
        if ((i & 3) == 3) ((float4*)whrow)[i >> 2] = buf;
    }
    g_src[row] = srcv;
    g_dst[row] = dstv;
    g_A[row] = expf(srcv);
    g_C[row] = expf(0.2f * srcv);
    g_B[row] = expf(dstv);
    g_D[row] = expf(0.2f * dstv);
}

// ---------------- attention: x_out = relu( softmax(mask(e)) @ Wh ) ----------------
// One CTA per BI=32 rows of i; stream over j in BJ=64 chunks.
// w_ij = adj ? ((src_i+dst_j>0) ? A_i*B_j : C_i*D_j) : 0   (no exp in inner loop)
__global__ void __launch_bounds__(TPB) attn_kernel(const int* __restrict__ adj) {
    __shared__ float wh_s[BJ * DH];     // 16 KB, [k][d]
    __shared__ float w_s[BJ * 34];      // 8.5 KB, [k][i] stride 34 (align + bank-safe)
    __shared__ float dpart[TPB];
    __shared__ float dinv[BI];

    int t = threadIdx.x;
    int i0 = blockIdx.x * BI;

    // phase-A mapping: each thread owns one i-row, 8 k's per chunk
    int i_loc = t >> 3, g = t & 7;
    int irow = i0 + i_loc;
    float s_i = g_src[irow];
    float aA = g_A[irow], cC = g_C[irow];
    float dsum = 0.f;

    // GEMM mapping: 16x16 thread grid -> 2 rows x 4 cols per thread
    int tx = t & 15, ty = t >> 4;
    unsigned long long a00 = 0ull, a01 = 0ull, a10 = 0ull, a11 = 0ull;

    const int4* adjrow = (const int4*)(adj + (size_t)irow * NN);

    int4 adjr[2];
    float4 whr[4];
    // prefetch chunk 0
#pragma unroll
    for (int it = 0; it < 2; it++) adjr[it] = adjrow[g + it * 8];
#pragma unroll
    for (int r = 0; r < 4; r++) whr[r] = ((const float4*)g_Wh)[t + r * TPB];

    for (int c = 0; c < NCHUNK; c++) {
        int j0 = c * BJ;

        // ---- phase A: stage Wh tile + compute weight tile ----
#pragma unroll
        for (int r = 0; r < 4; r++) ((float4*)wh_s)[t + r * TPB] = whr[r];

#pragma unroll
        for (int it = 0; it < 2; it++) {
            int k = g * 4 + it * 32;
            int4 a4 = adjr[it];
            float4 dv  = *(const float4*)(g_dst + j0 + k);
            float4 bv  = *(const float4*)(g_B + j0 + k);
            float4 ddv = *(const float4*)(g_D + j0 + k);
            float w0, w1, w2, w3;
            { float s = s_i + dv.x; float p = s > 0.f ? aA : cC; float q = s > 0.f ? bv.x : ddv.x; w0 = a4.x ? p * q : 0.f; }
            { float s = s_i + dv.y; float p = s > 0.f ? aA : cC; float q = s > 0.f ? bv.y : ddv.y; w1 = a4.y ? p * q : 0.f; }
            { float s = s_i + dv.z; float p = s > 0.f ? aA : cC; float q = s > 0.f ? bv.z : ddv.z; w2 = a4.z ? p * q : 0.f; }
            { float s = s_i + dv.w; float p = s > 0.f ? aA : cC; float q = s > 0.f ? bv.w : ddv.w; w3 = a4.w ? p * q : 0.f; }
            dsum += (w0 + w1) + (w2 + w3);
            w_s[(k + 0) * 34 + i_loc] = w0;
            w_s[(k + 1) * 34 + i_loc] = w1;
            w_s[(k + 2) * 34 + i_loc] = w2;
            w_s[(k + 3) * 34 + i_loc] = w3;
        }
        __syncthreads();

        // ---- prefetch next chunk (LDG latency hides under GEMM) ----
        if (c + 1 < NCHUNK) {
            int j1 = j0 + BJ;
#pragma unroll
            for (int it = 0; it < 2; it++) adjr[it] = adjrow[(j1 >> 2) + g + it * 8];
#pragma unroll
            for (int r = 0; r < 4; r++)
                whr[r] = ((const float4*)g_Wh)[(size_t)j1 * (DH / 4) + t + r * TPB];
        }

        // ---- phase B: C[32x64] += W[32 x BJ] * Wh[BJ x 64] with FFMA2 ----
#pragma unroll 8
        for (int k = 0; k < BJ; k++) {
            float2 wp = *(const float2*)(w_s + k * 34 + ty * 2);
            ulonglong2 h = *(const ulonglong2*)(wh_s + k * DH + tx * 4);
            unsigned long long wq0 = pack2(wp.x, wp.x);
            unsigned long long wq1 = pack2(wp.y, wp.y);
            a00 = ffma2(wq0, h.x, a00);
            a01 = ffma2(wq0, h.y, a01);
            a10 = ffma2(wq1, h.x, a10);
            a11 = ffma2(wq1, h.y, a11);
        }
        __syncthreads();
    }

    // ---- row denominators (softmax normalization) ----
    dpart[t] = dsum;   // t == i_loc*8 + g
    __syncthreads();
    if (t < BI) {
        float d = 0.f;
#pragma unroll
        for (int q = 0; q < 8; q++) d += dpart[t * 8 + q];
        dinv[t] = 1.0f / d;
    }
    __syncthreads();

    float inv0 = dinv[ty * 2], inv1 = dinv[ty * 2 + 1];
    float o0, o1, o2, o3;
    float4 outv;

    unpack2(a00, o0, o1); unpack2(a01, o2, o3);
    outv.x = fmaxf(o0 * inv0, 0.f); outv.y = fmaxf(o1 * inv0, 0.f);
    outv.z = fmaxf(o2 * inv0, 0.f); outv.w = fmaxf(o3 * inv0, 0.f);
    ((float4*)(g_x + (size_t)(i0 + ty * 2) * DH))[tx] = outv;

    unpack2(a10, o0, o1); unpack2(a11, o2, o3);
    outv.x = fmaxf(o0 * inv1, 0.f); outv.y = fmaxf(o1 * inv1, 0.f);
    outv.z = fmaxf(o2 * inv1, 0.f); outv.w = fmaxf(o3 * inv1, 0.f);
    ((float4*)(g_x + (size_t)(i0 + ty * 2 + 1) * DH))[tx] = outv;
}

// ---------------- final: out = x @ out_w^T + out_b ----------------
__global__ void final_kernel(const float* __restrict__ Wm, const float* __restrict__ bv,
                             float* __restrict__ out) {
    __shared__ float Ws[DH * DH];
    __shared__ float bs[DH];
    int t = threadIdx.x;
    for (int k = t; k < DH * DH; k += 128) Ws[k] = Wm[k];
    if (t < DH) bs[t] = bv[t];
    __syncthreads();

    int row = blockIdx.x * 128 + t;
    const float* xr = g_x + (size_t)row * DH;
    float x[DH];
#pragma unroll
    for (int q = 0; q < DH / 4; q++) {
        float4 v = ((const float4*)xr)[q];
        x[4 * q + 0] = v.x; x[4 * q + 1] = v.y; x[4 * q + 2] = v.z; x[4 * q + 3] = v.w;
    }
    float4 buf;
    float* orow = out + (size_t)row * DH;
    for (int i = 0; i < DH; i++) {
        float acc = bs[i];
#pragma unroll
        for (int j = 0; j < DH; j++) acc += x[j] * Ws[i * DH + j];
        ((float*)&buf)[i & 3] = acc;
        if ((i & 3) == 3) ((float4*)orow)[i >> 2] = buf;
    }
}

// ---------------- launch ----------------
extern "C" void kernel_launch(void* const* d_in, const int* in_sizes, int n_in,
                              void* d_out, int out_size) {
    const int*   adj  = (const int*)d_in[0];
    const float* user = (const float*)d_in[1];
    const float* item = (const float*)d_in[2];
    const float* W0   = (const float*)d_in[3];
    const float* b0   = (const float*)d_in[4];
    const float* a0   = (const float*)d_in[5];
    const float* W1   = (const float*)d_in[6];
    const float* b1   = (const float*)d_in[7];
    const float* a1   = (const float*)d_in[8];
    const float* ow   = (const float*)d_in[9];
    const float* ob   = (const float*)d_in[10];

    prep_kernel<<<NN / 128, 128>>>(user, item, W0, b0, a0, 0);
    attn_kernel<<<NN / BI, TPB>>>(adj);
    prep_kernel<<<NN / 128, 128>>>(nullptr, nullptr, W1, b1, a1, 1);
    attn_kernel<<<NN / BI, TPB>>>(adj);
    final_kernel<<<NN / 128, 128>>>(ow, ob, (float*)d_out);
}

// round 4
// speedup vs baseline: 2.6128x; 2.6128x over previous
#include <cuda_runtime.h>
#include <cuda_fp16.h>
#include <stdint.h>

#define NN 8192
#define DH 64
#define NCOL 80            // 64 cols + denom col(64) + 15 zero pad
#define KC 64              // j's per chunk
#define KSPLIT 2
#define KHALF (NN / KSPLIT)
#define NCH (KHALF / KC)   // 64 chunks
#define TPB 512
// smem: W tile 128x64 fp16 (16KB) x2, B tile 80x64 fp16 (10KB) x2
#define WOFF0 0
#define WOFF1 16384
#define BOFF0 32768
#define BOFF1 43008
#define SMEM_BYTES 53248

// ---------------- device scratch ----------------
__device__ unsigned g_adjp[NN * 256];          // packed adjacency bits (8MB)
__device__ unsigned short g_WhT[NCOL * NN];    // Wh^T fp16 [80][8192]; row64=1, 65..79=0
__device__ float4 g_srcACC[NN];                // {src, exp(src), exp(.2src), 0}
__device__ float4 g_dstBDD[NN];                // {dst, exp(dst), exp(.2dst), 0}
__device__ float g_part[KSPLIT * NN * NCOL];   // K-split partials
__device__ float g_x[NN * DH];

// ---------------- helpers ----------------
__device__ __forceinline__ uint32_t smem_u32(const void* p) {
    uint32_t a;
    asm("{ .reg .u64 t; cvta.to.shared.u64 t, %1; cvt.u32.u64 %0, t; }" : "=r"(a) : "l"(p));
    return a;
}
#define SWZ(off) ((off) ^ (((off) >> 3) & 0x70))

__device__ __forceinline__ void ldsm_x4(uint32_t& r0, uint32_t& r1, uint32_t& r2, uint32_t& r3,
                                        uint32_t a) {
    asm volatile("ldmatrix.sync.aligned.m8n8.x4.shared.b16 {%0,%1,%2,%3}, [%4];"
                 : "=r"(r0), "=r"(r1), "=r"(r2), "=r"(r3) : "r"(a));
}
__device__ __forceinline__ void ldsm_x2(uint32_t& r0, uint32_t& r1, uint32_t a) {
    asm volatile("ldmatrix.sync.aligned.m8n8.x2.shared.b16 {%0,%1}, [%2];"
                 : "=r"(r0), "=r"(r1) : "r"(a));
}
__device__ __forceinline__ void mma16816(float* d, const uint32_t* a, const uint32_t* b) {
    asm volatile("mma.sync.aligned.m16n8k16.row.col.f32.f16.f16.f32 "
                 "{%0,%1,%2,%3}, {%4,%5,%6,%7}, {%8,%9}, {%0,%1,%2,%3};"
                 : "+f"(d[0]), "+f"(d[1]), "+f"(d[2]), "+f"(d[3])
                 : "r"(a[0]), "r"(a[1]), "r"(a[2]), "r"(a[3]), "r"(b[0]), "r"(b[1]));
}

// ---------------- pack adjacency to bits ----------------
__global__ void __launch_bounds__(256) pack_kernel(const int* __restrict__ adj) {
    int row = blockIdx.x, t = threadIdx.x, w = t >> 5, lane = t & 31;
    const int* r = adj + (size_t)row * NN;
#pragma unroll 4
    for (int k = 0; k < 32; k++) {
        int v = r[k * 256 + t];
        unsigned m = __ballot_sync(0xffffffffu, v != 0);
        if (lane == 0) g_adjp[row * 256 + k * 8 + w] = m;
    }
}

// ---------------- prep: Wh^T fp16, src/dst exp factors ----------------
__global__ void __launch_bounds__(64) prep_kernel(const float* __restrict__ xa,
                                                  const float* __restrict__ xb,
                                                  const float* __restrict__ Wm,
                                                  const float* __restrict__ bv,
                                                  const float* __restrict__ av, int use_gx) {
    __shared__ float Ws[DH * DH];
    __shared__ float as_[2 * DH];
    __shared__ float bs[DH];
    int t = threadIdx.x;
    for (int k = t; k < DH * DH; k += 64) Ws[k] = Wm[k];
    if (t < DH) { as_[t] = av[t]; as_[DH + t] = av[DH + t]; bs[t] = bv[t]; }
    __syncthreads();

    int row = blockIdx.x * 64 + t;
    const float* xr = use_gx ? (g_x + (size_t)row * DH)
                             : (row < NN / 2 ? xa + (size_t)row * DH
                                             : xb + (size_t)(row - NN / 2) * DH);
    float x[DH];
#pragma unroll
    for (int q = 0; q < 16; q++) {
        float4 v = ((const float4*)xr)[q];
        x[4 * q] = v.x; x[4 * q + 1] = v.y; x[4 * q + 2] = v.z; x[4 * q + 3] = v.w;
    }
    float srcv = 0.f, dstv = 0.f;
    for (int i = 0; i < DH; i++) {
        const float4* w4 = (const float4*)(Ws + i * DH);
        float a0 = 0.f, a1 = 0.f, a2 = 0.f, a3 = 0.f;
#pragma unroll
        for (int q = 0; q < 16; q += 4) {
            float4 w;
            w = w4[q];     a0 = fmaf(x[4*q+3], w.w, fmaf(x[4*q+2], w.z, fmaf(x[4*q+1], w.y, fmaf(x[4*q], w.x, a0))));
            w = w4[q + 1]; a1 = fmaf(x[4*q+7], w.w, fmaf(x[4*q+6], w.z, fmaf(x[4*q+5], w.y, fmaf(x[4*q+4], w.x, a1))));
            w = w4[q + 2]; a2 = fmaf(x[4*q+11], w.w, fmaf(x[4*q+10], w.z, fmaf(x[4*q+9], w.y, fmaf(x[4*q+8], w.x, a2))));
            w = w4[q + 3]; a3 = fmaf(x[4*q+15], w.w, fmaf(x[4*q+14], w.z, fmaf(x[4*q+13], w.y, fmaf(x[4*q+12], w.x, a3))));
        }
        float wh = bs[i] + ((a0 + a1) + (a2 + a3));
        srcv = fmaf(wh, as_[i], srcv);
        dstv = fmaf(wh, as_[DH + i], dstv);
        g_WhT[(size_t)i * NN + row] = __half_as_ushort(__float2half_rn(wh));
    }
    g_WhT[(size_t)64 * NN + row] = __half_as_ushort(__float2half_rn(1.0f));
#pragma unroll
    for (int d = 65; d < NCOL; d++) g_WhT[(size_t)d * NN + row] = 0;
    g_srcACC[row] = make_float4(srcv, expf(srcv), expf(0.2f * srcv), 0.f);
    g_dstBDD[row] = make_float4(dstv, expf(dstv), expf(0.2f * dstv), 0.f);
}

// ---------------- attn: HMMA flash-GAT ----------------
// grid 128: blockIdx = tile*KSPLIT + ks. Tile = 128 i rows.
__global__ void __launch_bounds__(TPB, 1) attn_mma() {
    extern __shared__ char smem[];
    uint32_t sb = smem_u32(smem);
    int t = threadIdx.x, wid = t >> 5, lane = t & 31;
    int tile = blockIdx.x >> 1, ks = blockIdx.x & 1;
    int i0 = tile * 128, jbase = ks * KHALF;

    // ---- weight-gen mapping: thread t -> row i_loc, 16 j's at jq ----
    int i_loc = t >> 2;
    int jq = (t & 3) * 16;
    float4 sac = g_srcACC[i0 + i_loc];
    const unsigned* apt = g_adjp + (size_t)(i0 + i_loc) * 256 + (jbase >> 5) + (jq >> 5);
    int shft = jq & 16;
    uint32_t wdst0 = SWZ((uint32_t)(i_loc * 128 + jq * 2));
    uint32_t wdst1 = SWZ((uint32_t)(i_loc * 128 + jq * 2 + 16));
    const float4* jbp = g_dstBDD + jbase + jq;

    // ---- B-tile copy mapping ----
    int bn0 = t >> 3, bq0 = t & 7;
    uint32_t bdst0 = SWZ((uint32_t)(bn0 * 128 + bq0 * 16));
    const uint4* bsrc0 = (const uint4*)(g_WhT + (size_t)bn0 * NN + jbase) + bq0;
    int bn1 = 64 + (t >> 3);
    uint32_t bdst1 = SWZ((uint32_t)(bn1 * 128 + bq0 * 16));
    const uint4* bsrc1 = (const uint4*)(g_WhT + (size_t)bn1 * NN + jbase) + bq0;

    // ---- GEMM mapping: 16 warps = 8 M-tiles x 2 N-halves(40) ----
    int wm = wid & 7, wn = wid >> 3;
    float acc[5][4];
#pragma unroll
    for (int n = 0; n < 5; n++)
#pragma unroll
        for (int q = 0; q < 4; q++) acc[n][q] = 0.f;

    // ldmatrix address offsets (within tile, before buffer base)
    int lr = lane & 7, lsel = lane >> 3;
    // A x4: row = wm*16 + lr + (lsel&1)*8, k = (lsel>>1)*8  (+16 per k-step)
    uint32_t a_off = SWZ((uint32_t)((wm * 16 + lr + (lsel & 1) * 8) * 128 + ((lsel >> 1) * 8) * 2));
    // B x4 (ntile pair base nt): n = wn*40 + nt*8 + lr + (lsel>>1)*8, k = (lsel&1)*8
    uint32_t b_off_pair = SWZ((uint32_t)((wn * 40 + lr + (lsel >> 1) * 8) * 128 + ((lsel & 1) * 8) * 2));
    // B x2 (5th ntile): n = wn*40 + 32 + lr, k = ((lane>>3)&1)*8
    uint32_t b_off_5 = SWZ((uint32_t)((wn * 40 + 32 + lr) * 128 + (((lane >> 3) & 1) * 8) * 2));

    // ---- stage chunk 0 ----
    {
        uint4* bd = (uint4*)(smem + BOFF0);
        *(uint4*)((char*)bd + bdst0) = bsrc0[0];
        if (t < 128) *(uint4*)((char*)bd + bdst1) = bsrc1[0];
        const float4* jp = jbp;
        unsigned wbits = apt[0] >> shft;
        uint32_t hh0[4], hh1[4];
#pragma unroll
        for (int k2 = 0; k2 < 4; k2++) {
            float w0, w1, w2, w3;
            { float4 j = jp[2*k2];   float s = sac.x + j.x; float wv = s > 0.f ? sac.y*j.y : sac.z*j.z; w0 = (wbits >> (2*k2)) & 1 ? wv : 0.f; }
            { float4 j = jp[2*k2+1]; float s = sac.x + j.x; float wv = s > 0.f ? sac.y*j.y : sac.z*j.z; w1 = (wbits >> (2*k2+1)) & 1 ? wv : 0.f; }
            { float4 j = jp[8+2*k2];   float s = sac.x + j.x; float wv = s > 0.f ? sac.y*j.y : sac.z*j.z; w2 = (wbits >> (8+2*k2)) & 1 ? wv : 0.f; }
            { float4 j = jp[8+2*k2+1]; float s = sac.x + j.x; float wv = s > 0.f ? sac.y*j.y : sac.z*j.z; w3 = (wbits >> (8+2*k2+1)) & 1 ? wv : 0.f; }
            __half2 ha = __floats2half2_rn(w0, w1); hh0[k2] = *(uint32_t*)&ha;
            __half2 hb = __floats2half2_rn(w2, w3); hh1[k2] = *(uint32_t*)&hb;
        }
        *(uint4*)(smem + WOFF0 + wdst0) = make_uint4(hh0[0], hh0[1], hh0[2], hh0[3]);
        *(uint4*)(smem + WOFF0 + wdst1) = make_uint4(hh1[0], hh1[1], hh1[2], hh1[3]);
    }
    __syncthreads();

    for (int c = 0; c < NCH; c++) {
        int buf = c & 1;
        // ---- stage chunk c+1 into other buffer ----
        if (c + 1 < NCH) {
            int nb = buf ^ 1;
            uint32_t bo = nb ? BOFF1 : BOFF0, wo = nb ? WOFF1 : WOFF0;
            *(uint4*)(smem + bo + bdst0) = bsrc0[(c + 1) * 8];
            if (t < 128) *(uint4*)(smem + bo + bdst1) = bsrc1[(c + 1) * 8];
            const float4* jp = jbp + (size_t)(c + 1) * KC;
            unsigned wbits = apt[(c + 1) * 2] >> shft;
            uint32_t hh0[4], hh1[4];
#pragma unroll
            for (int k2 = 0; k2 < 4; k2++) {
                float w0, w1, w2, w3;
                { float4 j = jp[2*k2];   float s = sac.x + j.x; float wv = s > 0.f ? sac.y*j.y : sac.z*j.z; w0 = (wbits >> (2*k2)) & 1 ? wv : 0.f; }
                { float4 j = jp[2*k2+1]; float s = sac.x + j.x; float wv = s > 0.f ? sac.y*j.y : sac.z*j.z; w1 = (wbits >> (2*k2+1)) & 1 ? wv : 0.f; }
                { float4 j = jp[8+2*k2];   float s = sac.x + j.x; float wv = s > 0.f ? sac.y*j.y : sac.z*j.z; w2 = (wbits >> (8+2*k2)) & 1 ? wv : 0.f; }
                { float4 j = jp[8+2*k2+1]; float s = sac.x + j.x; float wv = s > 0.f ? sac.y*j.y : sac.z*j.z; w3 = (wbits >> (8+2*k2+1)) & 1 ? wv : 0.f; }
                __half2 ha = __floats2half2_rn(w0, w1); hh0[k2] = *(uint32_t*)&ha;
                __half2 hb = __floats2half2_rn(w2, w3); hh1[k2] = *(uint32_t*)&hb;
            }
            *(uint4*)(smem + wo + wdst0) = make_uint4(hh0[0], hh0[1], hh0[2], hh0[3]);
            *(uint4*)(smem + wo + wdst1) = make_uint4(hh1[0], hh1[1], hh1[2], hh1[3]);
        }

        // ---- GEMM on chunk c ----
        uint32_t wbase = sb + (buf ? WOFF1 : WOFF0);
        uint32_t bbase = sb + (buf ? BOFF1 : BOFF0);
#pragma unroll
        for (int k = 0; k < 4; k++) {
            uint32_t kb = (uint32_t)(k * 32);  // 16 fp16 = 32 bytes per k-step
            uint32_t af[4], bf[10];
            ldsm_x4(af[0], af[1], af[2], af[3], wbase + (a_off ^ SWZ(kb)) ); // note: kb within 128B row: SWZ(x+kb)=SWZ(x)^... 
            // k offsets stay inside the 128B row so swizzle distributes over XOR of bits<7:
            // recompute directly to be safe:
            (void)kb;
            uint32_t a_adr = wbase + SWZ((uint32_t)((wm * 16 + lr + (lsel & 1) * 8) * 128 + ((lsel >> 1) * 8 + k * 16) * 2));
            ldsm_x4(af[0], af[1], af[2], af[3], a_adr);
#pragma unroll
            for (int p = 0; p < 2; p++) {
                uint32_t b_adr = bbase + SWZ((uint32_t)((wn * 40 + p * 16 + lr + (lsel >> 1) * 8) * 128 + ((lsel & 1) * 8 + k * 16) * 2));
                ldsm_x4(bf[p * 4 + 0], bf[p * 4 + 1], bf[p * 4 + 2], bf[p * 4 + 3], b_adr);
            }
            {
                uint32_t b_adr = bbase + SWZ((uint32_t)((wn * 40 + 32 + lr) * 128 + ((((lane >> 3) & 1) * 8) + k * 16) * 2));
                ldsm_x2(bf[8], bf[9], b_adr);
            }
            mma16816(acc[0], af, bf + 0);
            mma16816(acc[1], af, bf + 2);
            mma16816(acc[2], af, bf + 4);
            mma16816(acc[3], af, bf + 6);
            mma16816(acc[4], af, bf + 8);
        }
        __syncthreads();
    }

    // ---- epilogue: write partials ----
    int row0 = i0 + wm * 16 + (lane >> 2);
    float* base = g_part + ((size_t)ks * NN) * NCOL;
#pragma unroll
    for (int nt = 0; nt < 5; nt++) {
        int col = wn * 40 + nt * 8 + (lane & 3) * 2;
        *(float2*)(base + (size_t)row0 * NCOL + col) = make_float2(acc[nt][0], acc[nt][1]);
        *(float2*)(base + (size_t)(row0 + 8) * NCOL + col) = make_float2(acc[nt][2], acc[nt][3]);
    }
}

// ---------------- combine K-split partials + normalize + relu ----------------
__global__ void __launch_bounds__(256) combine_kernel() {
    int t = threadIdx.x;
    int row = blockIdx.x * 4 + (t >> 6);
    int c = t & 63;
    const float* p0 = g_part + (size_t)row * NCOL;
    const float* p1 = g_part + (size_t)NN * NCOL + (size_t)row * NCOL;
    float den = p0[64] + p1[64];
    float v = (p0[c] + p1[c]) / den;
    g_x[(size_t)row * DH + c] = v > 0.f ? v : 0.f;
}

// ---------------- final: out = x @ out_w^T + out_b ----------------
__global__ void __launch_bounds__(64) final_kernel(const float* __restrict__ Wm,
                                                   const float* __restrict__ bv,
                                                   float* __restrict__ out) {
    __shared__ float Ws[DH * DH];
    __shared__ float bs[DH];
    int t = threadIdx.x;
    for (int k = t; k < DH * DH; k += 64) Ws[k] = Wm[k];
    if (t < DH) bs[t] = bv[t];
    __syncthreads();

    int row = blockIdx.x * 64 + t;
    const float* xr = g_x + (size_t)row * DH;
    float x[DH];
#pragma unroll
    for (int q = 0; q < 16; q++) {
        float4 v = ((const float4*)xr)[q];
        x[4 * q] = v.x; x[4 * q + 1] = v.y; x[4 * q + 2] = v.z; x[4 * q + 3] = v.w;
    }
    float* orow = out + (size_t)row * DH;
    for (int i = 0; i < DH; i += 4) {
        float4 res;
#pragma unroll
        for (int u = 0; u < 4; u++) {
            const float4* w4 = (const float4*)(Ws + (i + u) * DH);
            float a0 = 0.f, a1 = 0.f, a2 = 0.f, a3 = 0.f;
#pragma unroll
            for (int q = 0; q < 16; q += 4) {
                float4 w;
                w = w4[q];     a0 = fmaf(x[4*q+3], w.w, fmaf(x[4*q+2], w.z, fmaf(x[4*q+1], w.y, fmaf(x[4*q], w.x, a0))));
                w = w4[q + 1]; a1 = fmaf(x[4*q+7], w.w, fmaf(x[4*q+6], w.z, fmaf(x[4*q+5], w.y, fmaf(x[4*q+4], w.x, a1))));
                w = w4[q + 2]; a2 = fmaf(x[4*q+11], w.w, fmaf(x[4*q+10], w.z, fmaf(x[4*q+9], w.y, fmaf(x[4*q+8], w.x, a2))));
                w = w4[q + 3]; a3 = fmaf(x[4*q+15], w.w, fmaf(x[4*q+14], w.z, fmaf(x[4*q+13], w.y, fmaf(x[4*q+12], w.x, a3))));
            }
            ((float*)&res)[u] = bs[i + u] + ((a0 + a1) + (a2 + a3));
        }
        ((float4*)orow)[i >> 2] = res;
    }
}

// ---------------- launch ----------------
extern "C" void kernel_launch(void* const* d_in, const int* in_sizes, int n_in,
                              void* d_out, int out_size) {
    const int*   adj  = (const int*)d_in[0];
    const float* user = (const float*)d_in[1];
    const float* item = (const float*)d_in[2];
    const float* W0   = (const float*)d_in[3];
    const float* b0   = (const float*)d_in[4];
    const float* a0   = (const float*)d_in[5];
    const float* W1   = (const float*)d_in[6];
    const float* b1   = (const float*)d_in[7];
    const float* a1   = (const float*)d_in[8];
    const float* ow   = (const float*)d_in[9];
    const float* ob   = (const float*)d_in[10];

    cudaFuncSetAttribute(attn_mma, cudaFuncAttributeMaxDynamicSharedMemorySize, SMEM_BYTES);

    pack_kernel<<<NN, 256>>>(adj);
    prep_kernel<<<NN / 64, 64>>>(user, item, W0, b0, a0, 0);
    attn_mma<<<64 * KSPLIT, TPB, SMEM_BYTES>>>();
    combine_kernel<<<NN / 4, 256>>>();
    prep_kernel<<<NN / 64, 64>>>(nullptr, nullptr, W1, b1, a1, 1);
    attn_mma<<<64 * KSPLIT, TPB, SMEM_BYTES>>>();
    combine_kernel<<<NN / 4, 256>>>();
    final_kernel<<<NN / 64, 64>>>(ow, ob, (float*)d_out);
}

// round 5
// speedup vs baseline: 4.6930x; 1.7961x over previous
#include <cuda_runtime.h>
#include <cuda_fp16.h>
#include <stdint.h>

#define NN 8192
#define DH 64
#define NCOL 80            // 64 cols + denom col(64) + 15 zero pad
#define KC 64              // j's per chunk
#define KSPLIT 2
#define KHALF (NN / KSPLIT)
#define NCH (KHALF / KC)   // 64 chunks
#define TPB 256
#define TILE_I 64
// smem: W tile 64x64 fp16 (8KB) x2, B tile 80x64 fp16 (10KB) x2
#define WOFF0 0
#define WOFF1 8192
#define BOFF0 16384
#define BOFF1 26624
#define SMEM_BYTES 36864

// ---------------- device scratch ----------------
__device__ unsigned short g_adjp[NN * 512];    // packed adjacency bits (8MB), ushort granular
__device__ unsigned short g_WhT[NCOL * NN];    // Wh^T fp16 [80][8192]; row64=1, 65..79=0
__device__ uint2 g_iAC[NN];                    // {half2(expf(src)), half2(expf(.2src))}
__device__ unsigned short g_jB[NN];            // half expf(dst)
__device__ unsigned short g_jD[NN];            // half expf(.2 dst)
__device__ float g_part[KSPLIT * NN * NCOL];   // K-split partials
__device__ float g_x[NN * DH];

// ---------------- helpers ----------------
__device__ __forceinline__ uint32_t smem_u32(const void* p) {
    uint32_t a;
    asm("{ .reg .u64 t; cvta.to.shared.u64 t, %1; cvt.u32.u64 %0, t; }" : "=r"(a) : "l"(p));
    return a;
}
#define SWZ(off) ((off) ^ (((off) >> 3) & 0x70))

#define CPA16(d, s) asm volatile("cp.async.cg.shared.global [%0], [%1], 16;" :: "r"(d), "l"(s))
#define CPA_COMMIT() asm volatile("cp.async.commit_group;" ::: "memory")
#define CPA_WAIT0()  asm volatile("cp.async.wait_group 0;" ::: "memory")

__device__ __forceinline__ void ldsm_x4(uint32_t& r0, uint32_t& r1, uint32_t& r2, uint32_t& r3,
                                        uint32_t a) {
    asm volatile("ldmatrix.sync.aligned.m8n8.x4.shared.b16 {%0,%1,%2,%3}, [%4];"
                 : "=r"(r0), "=r"(r1), "=r"(r2), "=r"(r3) : "r"(a));
}
__device__ __forceinline__ void ldsm_x2(uint32_t& r0, uint32_t& r1, uint32_t a) {
    asm volatile("ldmatrix.sync.aligned.m8n8.x2.shared.b16 {%0,%1}, [%2];"
                 : "=r"(r0), "=r"(r1) : "r"(a));
}
__device__ __forceinline__ void mma16816(float* d, const uint32_t* a, const uint32_t* b) {
    asm volatile("mma.sync.aligned.m16n8k16.row.col.f32.f16.f16.f32 "
                 "{%0,%1,%2,%3}, {%4,%5,%6,%7}, {%8,%9}, {%0,%1,%2,%3};"
                 : "+f"(d[0]), "+f"(d[1]), "+f"(d[2]), "+f"(d[3])
                 : "r"(a[0]), "r"(a[1]), "r"(a[2]), "r"(a[3]), "r"(b[0]), "r"(b[1]));
}

// ---------------- prep: Wh^T fp16, per-node exp factors ----------------
__global__ void __launch_bounds__(64) prep_kernel(const float* __restrict__ xa,
                                                  const float* __restrict__ xb,
                                                  const float* __restrict__ Wm,
                                                  const float* __restrict__ bv,
                                                  const float* __restrict__ av, int use_gx) {
    __shared__ float Ws[DH * DH];
    __shared__ float as_[2 * DH];
    __shared__ float bs[DH];
    int t = threadIdx.x;
    for (int k = t; k < DH * DH; k += 64) Ws[k] = Wm[k];
    if (t < DH) { as_[t] = av[t]; as_[DH + t] = av[DH + t]; bs[t] = bv[t]; }
    __syncthreads();

    int row = blockIdx.x * 64 + t;
    const float* xr = use_gx ? (g_x + (size_t)row * DH)
                             : (row < NN / 2 ? xa + (size_t)row * DH
                                             : xb + (size_t)(row - NN / 2) * DH);
    float x[DH];
#pragma unroll
    for (int q = 0; q < 16; q++) {
        float4 v = ((const float4*)xr)[q];
        x[4 * q] = v.x; x[4 * q + 1] = v.y; x[4 * q + 2] = v.z; x[4 * q + 3] = v.w;
    }
    float srcv = 0.f, dstv = 0.f;
    for (int i = 0; i < DH; i++) {
        const float4* w4 = (const float4*)(Ws + i * DH);
        float a0 = 0.f, a1 = 0.f, a2 = 0.f, a3 = 0.f;
#pragma unroll
        for (int q = 0; q < 16; q += 4) {
            float4 w;
            w = w4[q];     a0 = fmaf(x[4*q+3], w.w, fmaf(x[4*q+2], w.z, fmaf(x[4*q+1], w.y, fmaf(x[4*q], w.x, a0))));
            w = w4[q + 1]; a1 = fmaf(x[4*q+7], w.w, fmaf(x[4*q+6], w.z, fmaf(x[4*q+5], w.y, fmaf(x[4*q+4], w.x, a1))));
            w = w4[q + 2]; a2 = fmaf(x[4*q+11], w.w, fmaf(x[4*q+10], w.z, fmaf(x[4*q+9], w.y, fmaf(x[4*q+8], w.x, a2))));
            w = w4[q + 3]; a3 = fmaf(x[4*q+15], w.w, fmaf(x[4*q+14], w.z, fmaf(x[4*q+13], w.y, fmaf(x[4*q+12], w.x, a3))));
        }
        float wh = bs[i] + ((a0 + a1) + (a2 + a3));
        srcv = fmaf(wh, as_[i], srcv);
        dstv = fmaf(wh, as_[DH + i], dstv);
        g_WhT[(size_t)i * NN + row] = __half_as_ushort(__float2half_rn(wh));
    }
    g_WhT[(size_t)64 * NN + row] = __half_as_ushort(__float2half_rn(1.0f));
#pragma unroll
    for (int d = 65; d < NCOL; d++) g_WhT[(size_t)d * NN + row] = 0;

    __half2 Ah = __float2half2_rn(expf(srcv));
    __half2 Ch = __float2half2_rn(expf(0.2f * srcv));
    g_iAC[row] = make_uint2(*(uint32_t*)&Ah, *(uint32_t*)&Ch);
    g_jB[row] = __half_as_ushort(__float2half_rn(expf(dstv)));
    g_jD[row] = __half_as_ushort(__float2half_rn(expf(0.2f * dstv)));
}

// ---------------- weight-tile generation (half2, no sign test) ----------------
template<int L0>
__device__ __forceinline__ void gen_store(char* smemp, uint32_t wo, uint32_t wdst0, uint32_t wdst1,
                                          uint32_t A2, uint32_t C2,
                                          const uint4& B0, const uint4& B1,
                                          const uint4& D0, const uint4& D1,
                                          uint32_t bits_in, const int* vi,
                                          unsigned short* packdst) {
    uint32_t Bw[8] = {B0.x, B0.y, B0.z, B0.w, B1.x, B1.y, B1.z, B1.w};
    uint32_t Dw[8] = {D0.x, D0.y, D0.z, D0.w, D1.x, D1.y, D1.z, D1.w};
    uint32_t wv[8];
    uint32_t packbits = 0;
    __half2 A2h = *(__half2*)&A2, C2h = *(__half2*)&C2;
#pragma unroll
    for (int p = 0; p < 8; p++) {
        __half2 ab = __hmul2(A2h, *(__half2*)&Bw[p]);
        __half2 cd = __hmul2(C2h, *(__half2*)&Dw[p]);
        __half2 w = __hmax2(ab, cd);      // = exp(leaky_relu(src+dst))
        uint32_t m;
        if (L0) {
            int v0 = vi[2 * p], v1 = vi[2 * p + 1];
            m = (v0 != 0 ? 0x0000FFFFu : 0u) | (v1 != 0 ? 0xFFFF0000u : 0u);
            packbits |= (v0 != 0 ? 1u : 0u) << (2 * p);
            packbits |= (v1 != 0 ? 1u : 0u) << (2 * p + 1);
        } else {
            uint32_t e = (bits_in >> (2 * p)) & 3u;
            uint32_t xm = (e * 0x8001u) & 0x10001u;
            m = xm * 0xFFFFu;             // 0xFFFF per set bit, per half
        }
        wv[p] = (*(uint32_t*)&w) & m;
    }
    *(uint4*)(smemp + wo + wdst0) = make_uint4(wv[0], wv[1], wv[2], wv[3]);
    *(uint4*)(smemp + wo + wdst1) = make_uint4(wv[4], wv[5], wv[6], wv[7]);
    if (L0) *packdst = (unsigned short)packbits;
}

// ---------------- attn: HMMA flash-GAT, 64x4096 per CTA ----------------
template<int L0>
__global__ void __launch_bounds__(TPB, 2) attn_mma(const int* __restrict__ adj) {
    extern __shared__ char smem[];
    uint32_t sb = smem_u32(smem);
    int t = threadIdx.x, wid = t >> 5, lane = t & 31;
    int tile = blockIdx.x >> 1, ks = blockIdx.x & 1;
    int i0 = tile * TILE_I, jbase = ks * KHALF;

    // ---- gen mapping: thread -> row i_loc, 16 j's ----
    int i_loc = t >> 2, jq16 = t & 3;
    int irow = i0 + i_loc;
    uint2 ac = g_iAC[irow];
    uint32_t wdst0 = SWZ((uint32_t)(i_loc * 128 + jq16 * 32));
    uint32_t wdst1 = SWZ((uint32_t)(i_loc * 128 + jq16 * 32 + 16));
    const uint4* pB = (const uint4*)(g_jB + jbase) + jq16 * 2;
    const uint4* pD = (const uint4*)(g_jD + jbase) + jq16 * 2;
    const int4* pAdj = (const int4*)(adj + (size_t)irow * NN + jbase) + jq16 * 4;
    unsigned short* pPack = g_adjp + (size_t)irow * 512 + (jbase >> 4) + jq16;

    // ---- B staging mapping (cp.async): 640 16B segs ----
    int s0 = t, s1 = t + 256, s2 = t + 512;
    uint32_t bd0 = SWZ((uint32_t)((s0 >> 3) * 128 + (s0 & 7) * 16));
    uint32_t bd1 = SWZ((uint32_t)((s1 >> 3) * 128 + (s1 & 7) * 16));
    uint32_t bd2 = SWZ((uint32_t)((s2 >> 3) * 128 + (s2 & 7) * 16));
    const unsigned short* bs0p = g_WhT + (size_t)(s0 >> 3) * NN + jbase + (s0 & 7) * 8;
    const unsigned short* bs1p = g_WhT + (size_t)(s1 >> 3) * NN + jbase + (s1 & 7) * 8;
    const unsigned short* bs2p = g_WhT + (size_t)(s2 >> 3) * NN + jbase + (s2 & 7) * 8;

    // ---- GEMM mapping: 8 warps = 4 M-tiles x 2 N-halves ----
    int wm = wid & 3, wn = wid >> 2;
    int lr = lane & 7, lsel = lane >> 3;
    float acc[5][4];
#pragma unroll
    for (int n = 0; n < 5; n++)
#pragma unroll
        for (int q = 0; q < 4; q++) acc[n][q] = 0.f;

    // ---- prefetch regs for chunk 0 ----
    uint4 Bq0 = pB[0], Bq1 = pB[1], Dq0 = pD[0], Dq1 = pD[1];
    uint32_t bits = 0;
    int4 rv[4];
    if (L0) { rv[0] = pAdj[0]; rv[1] = pAdj[1]; rv[2] = pAdj[2]; rv[3] = pAdj[3]; }
    else bits = pPack[0];

    // ---- stage chunk 0 ----
    CPA16(sb + BOFF0 + bd0, bs0p);
    CPA16(sb + BOFF0 + bd1, bs1p);
    if (t < 128) CPA16(sb + BOFF0 + bd2, bs2p);
    CPA_COMMIT();
    gen_store<L0>(smem, WOFF0, wdst0, wdst1, ac.x, ac.y, Bq0, Bq1, Dq0, Dq1,
                  bits, (const int*)rv, pPack);
    // prefetch chunk 1
    Bq0 = pB[8]; Bq1 = pB[9]; Dq0 = pD[8]; Dq1 = pD[9];
    if (L0) { rv[0] = pAdj[16]; rv[1] = pAdj[17]; rv[2] = pAdj[18]; rv[3] = pAdj[19]; }
    else bits = pPack[4];
    CPA_WAIT0();
    __syncthreads();

    for (int c = 0; c < NCH; c++) {
        int buf = c & 1;
        if (c + 1 < NCH) {
            int nb = buf ^ 1;
            uint32_t bo = nb ? BOFF1 : BOFF0, wo = nb ? WOFF1 : WOFF0;
            CPA16(sb + bo + bd0, bs0p + (c + 1) * 64);
            CPA16(sb + bo + bd1, bs1p + (c + 1) * 64);
            if (t < 128) CPA16(sb + bo + bd2, bs2p + (c + 1) * 64);
            CPA_COMMIT();
            gen_store<L0>(smem, wo, wdst0, wdst1, ac.x, ac.y, Bq0, Bq1, Dq0, Dq1,
                          bits, (const int*)rv, pPack + (c + 1) * 4);
            if (c + 2 < NCH) {
                Bq0 = pB[(c + 2) * 8]; Bq1 = pB[(c + 2) * 8 + 1];
                Dq0 = pD[(c + 2) * 8]; Dq1 = pD[(c + 2) * 8 + 1];
                if (L0) {
                    rv[0] = pAdj[(c + 2) * 16];     rv[1] = pAdj[(c + 2) * 16 + 1];
                    rv[2] = pAdj[(c + 2) * 16 + 2]; rv[3] = pAdj[(c + 2) * 16 + 3];
                } else bits = pPack[(c + 2) * 4];
            }
        }

        // ---- GEMM on chunk c ----
        uint32_t wbase = sb + (buf ? WOFF1 : WOFF0);
        uint32_t bbase = sb + (buf ? BOFF1 : BOFF0);
#pragma unroll
        for (int k = 0; k < 4; k++) {
            uint32_t af[4], bf[10];
            uint32_t a_adr = wbase + SWZ((uint32_t)((wm * 16 + lr + (lsel & 1) * 8) * 128 + ((lsel >> 1) * 8 + k * 16) * 2));
            ldsm_x4(af[0], af[1], af[2], af[3], a_adr);
#pragma unroll
            for (int p = 0; p < 2; p++) {
                uint32_t b_adr = bbase + SWZ((uint32_t)((wn * 40 + p * 16 + lr + (lsel >> 1) * 8) * 128 + ((lsel & 1) * 8 + k * 16) * 2));
                ldsm_x4(bf[p * 4 + 0], bf[p * 4 + 1], bf[p * 4 + 2], bf[p * 4 + 3], b_adr);
            }
            {
                uint32_t b_adr = bbase + SWZ((uint32_t)((wn * 40 + 32 + lr) * 128 + ((((lane >> 3) & 1) * 8) + k * 16) * 2));
                ldsm_x2(bf[8], bf[9], b_adr);
            }
            mma16816(acc[0], af, bf + 0);
            mma16816(acc[1], af, bf + 2);
            mma16816(acc[2], af, bf + 4);
            mma16816(acc[3], af, bf + 6);
            mma16816(acc[4], af, bf + 8);
        }
        CPA_WAIT0();
        __syncthreads();
    }

    // ---- epilogue: write partials ----
    int row0 = i0 + wm * 16 + (lane >> 2);
    float* base = g_part + ((size_t)ks * NN) * NCOL;
#pragma unroll
    for (int nt = 0; nt < 5; nt++) {
        int col = wn * 40 + nt * 8 + (lane & 3) * 2;
        *(float2*)(base + (size_t)row0 * NCOL + col) = make_float2(acc[nt][0], acc[nt][1]);
        *(float2*)(base + (size_t)(row0 + 8) * NCOL + col) = make_float2(acc[nt][2], acc[nt][3]);
    }
}

// ---------------- combine K-split partials + normalize + relu ----------------
__global__ void __launch_bounds__(256) combine_kernel() {
    int t = threadIdx.x;
    int row = blockIdx.x * 4 + (t >> 6);
    int c = t & 63;
    const float* p0 = g_part + (size_t)row * NCOL;
    const float* p1 = g_part + (size_t)NN * NCOL + (size_t)row * NCOL;
    float den = p0[64] + p1[64];
    float v = (p0[c] + p1[c]) / den;
    g_x[(size_t)row * DH + c] = v > 0.f ? v : 0.f;
}

// ---------------- final: out = x @ out_w^T + out_b ----------------
__global__ void __launch_bounds__(64) final_kernel(const float* __restrict__ Wm,
                                                   const float* __restrict__ bv,
                                                   float* __restrict__ out) {
    __shared__ float Ws[DH * DH];
    __shared__ float bs[DH];
    int t = threadIdx.x;
    for (int k = t; k < DH * DH; k += 64) Ws[k] = Wm[k];
    if (t < DH) bs[t] = bv[t];
    __syncthreads();

    int row = blockIdx.x * 64 + t;
    const float* xr = g_x + (size_t)row * DH;
    float x[DH];
#pragma unroll
    for (int q = 0; q < 16; q++) {
        float4 v = ((const float4*)xr)[q];
        x[4 * q] = v.x; x[4 * q + 1] = v.y; x[4 * q + 2] = v.z; x[4 * q + 3] = v.w;
    }
    float* orow = out + (size_t)row * DH;
    for (int i = 0; i < DH; i += 4) {
        float4 res;
#pragma unroll
        for (int u = 0; u < 4; u++) {
            const float4* w4 = (const float4*)(Ws + (i + u) * DH);
            float a0 = 0.f, a1 = 0.f, a2 = 0.f, a3 = 0.f;
#pragma unroll
            for (int q = 0; q < 16; q += 4) {
                float4 w;
                w = w4[q];     a0 = fmaf(x[4*q+3], w.w, fmaf(x[4*q+2], w.z, fmaf(x[4*q+1], w.y, fmaf(x[4*q], w.x, a0))));
                w = w4[q + 1]; a1 = fmaf(x[4*q+7], w.w, fmaf(x[4*q+6], w.z, fmaf(x[4*q+5], w.y, fmaf(x[4*q+4], w.x, a1))));
                w = w4[q + 2]; a2 = fmaf(x[4*q+11], w.w, fmaf(x[4*q+10], w.z, fmaf(x[4*q+9], w.y, fmaf(x[4*q+8], w.x, a2))));
                w = w4[q + 3]; a3 = fmaf(x[4*q+15], w.w, fmaf(x[4*q+14], w.z, fmaf(x[4*q+13], w.y, fmaf(x[4*q+12], w.x, a3))));
            }
            ((float*)&res)[u] = bs[i + u] + ((a0 + a1) + (a2 + a3));
        }
        ((float4*)orow)[i >> 2] = res;
    }
}

// ---------------- launch ----------------
extern "C" void kernel_launch(void* const* d_in, const int* in_sizes, int n_in,
                              void* d_out, int out_size) {
    const int*   adj  = (const int*)d_in[0];
    const float* user = (const float*)d_in[1];
    const float* item = (const float*)d_in[2];
    const float* W0   = (const float*)d_in[3];
    const float* b0   = (const float*)d_in[4];
    const float* a0   = (const float*)d_in[5];
    const float* W1   = (const float*)d_in[6];
    const float* b1   = (const float*)d_in[7];
    const float* a1   = (const float*)d_in[8];
    const float* ow   = (const float*)d_in[9];
    const float* ob   = (const float*)d_in[10];

    cudaFuncSetAttribute(attn_mma<1>, cudaFuncAttributeMaxDynamicSharedMemorySize, SMEM_BYTES);
    cudaFuncSetAttribute(attn_mma<0>, cudaFuncAttributeMaxDynamicSharedMemorySize, SMEM_BYTES);

    prep_kernel<<<NN / 64, 64>>>(user, item, W0, b0, a0, 0);
    attn_mma<1><<<(NN / TILE_I) * KSPLIT, TPB, SMEM_BYTES>>>(adj);   // fused: packs adj bits
    combine_kernel<<<NN / 4, 256>>>();
    prep_kernel<<<NN / 64, 64>>>(nullptr, nullptr, W1, b1, a1, 1);
    attn_mma<0><<<(NN / TILE_I) * KSPLIT, TPB, SMEM_BYTES>>>(adj);   // reads packed bits
    combine_kernel<<<NN / 4, 256>>>();
    final_kernel<<<NN / 64, 64>>>(ow, ob, (float*)d_out);
}